// round 10
// baseline (speedup 1.0000x reference)
#include <cuda_runtime.h>
#include <math.h>

typedef unsigned long long u64;

// ---------------------------------------------------------------------------
// f32x2 packed helpers (Blackwell dual-rate FP32 path)
// ---------------------------------------------------------------------------
__device__ __forceinline__ u64 pk(float lo, float hi) {
    u64 r;
    asm("mov.b64 %0, {%1,%2};" : "=l"(r) : "f"(lo), "f"(hi));
    return r;
}
__device__ __forceinline__ void upk(u64 v, float& lo, float& hi) {
    asm("mov.b64 {%0,%1}, %2;" : "=f"(lo), "=f"(hi) : "l"(v));
}
__device__ __forceinline__ u64 f2mul(u64 a, u64 b) {
    u64 r; asm("mul.rn.f32x2 %0, %1, %2;" : "=l"(r) : "l"(a), "l"(b)); return r;
}
__device__ __forceinline__ u64 f2add(u64 a, u64 b) {
    u64 r; asm("add.rn.f32x2 %0, %1, %2;" : "=l"(r) : "l"(a), "l"(b)); return r;
}
__device__ __forceinline__ u64 f2fma(u64 a, u64 b, u64 c) {
    u64 r; asm("fma.rn.f32x2 %0, %1, %2, %3;" : "=l"(r) : "l"(a), "l"(b), "l"(c)); return r;
}
__device__ __forceinline__ u64 f2sub(u64 a, u64 b) {
    u64 r; asm("sub.rn.f32x2 %0, %1, %2;" : "=l"(r) : "l"(a), "l"(b)); return r;
}
__device__ __forceinline__ u64 f2neg(u64 a) {
    return a ^ 0x8000000080000000ULL;  // sign-bit flip both lanes (ALU pipe, 4-cyc)
}

// complex multiply, sub-form: 5 issue slots, all fma-pipe
__device__ __forceinline__ void cmul(u64 ar, u64 ai, u64 br, u64 bi, u64& cr, u64& ci) {
    cr = f2sub(f2mul(ar, br), f2mul(ai, bi));
    ci = f2fma(ar, bi, f2mul(ai, br));
}

// ---------------------------------------------------------------------------
// Givens-form RY on qubit at bit M:  RY = cos(th/2) * [[1, -T],[T, 1]],
// T = tan(th/2); global cos factor applied as K^2 to the final z's.
// 4 FMA per pair, dependency depth 1.
// ---------------------------------------------------------------------------
template<int M>
__device__ __forceinline__ void ry_givens(u64* sr, u64* si, u64 tt, u64 nt) {
    #pragma unroll
    for (int i = 0; i < 16; ++i) {
        if (i & M) continue;
        const int j = i | M;
        u64 xr = f2fma(nt, sr[j], sr[i]);
        u64 xi = f2fma(nt, si[j], si[i]);
        sr[j] = f2fma(tt, sr[i], sr[j]);
        si[j] = f2fma(tt, si[i], si[j]);
        sr[i] = xr; si[i] = xi;
    }
}

#define SWAP_AMP(a, b) do { u64 _t = sr[a]; sr[a] = sr[b]; sr[b] = _t; \
                            _t = si[a]; si[a] = si[b]; si[b] = _t; } while (0)

// ---------------------------------------------------------------------------
// Single fused kernel, one batch-pair per thread, 3 CTAs/SM.
// All smem constant records are exactly 16B -> one LDS.128 each; negations
// are recomputed in registers on the (idle) ALU pipe instead of being extra
// 29-cycle shared loads (round-9 ncu: L1 19.8%, alu 2.9% -> rebalance).
//
// Circuit (algebraically reduced):
//   product-state encoding + dense layer-0 gate per wire (wire0 absorbs
//   phi_{1,0} fold), tensor product, CNOT0 (free swaps),
//   D1 = diag(phi_1, wires 1-3)  [8 phases, shared k / k+8],
//   RY(th_1) x4 (Givens),
//   D23 = diag(om_1 (+phi_{2,0} on w0)) * CNOT1-pullback(diag(phi_2)),
//   CNOT1 (free), RY(th_2) x4 (Givens), CNOT2 (free), |.|^2 * K^2,
//   butterfly Z.  (om_2 dropped: trailing diagonals don't change probs.)
// ---------------------------------------------------------------------------
__global__ void __launch_bounds__(256, 3)
qenc_kernel(const float4* __restrict__ x4, float4* __restrict__ out4,
            const float* __restrict__ params, int half) {
    __shared__ __align__(16) u64 s_l0[4][8];     // ar ai br bi cr ci dr di
    __shared__ __align__(16) u64 s_ry[8][2];     // T, -T (gate g = 4*(l-1)+q)
    __shared__ __align__(16) u64 s_d1[8][2];     // pr, pi
    __shared__ __align__(16) u64 s_d23[16][2];   // pr, pi
    __shared__ u64 s_k2;                         // (prod cos)^2, dup'd
    __shared__ float2 s_ph[32];                  // scratch phasors (cos, sin)

    const int tid = threadIdx.x;
    const int t = blockIdx.x * blockDim.x + tid;
    const bool active = (t < half);

    // Issue the global loads first — DRAM latency hides behind the prologue.
    float4 xa = active ? x4[t]        : make_float4(0.f, 0.f, 0.f, 0.f);
    float4 xb = active ? x4[t + half] : make_float4(0.f, 0.f, 0.f, 0.f);

    // ---- Prologue: warp 0 builds all gate-constant tables -----------------
    if (tid < 32) {
        if (tid < 31) {
            float ang;
            if (tid < 4) {                       // layer0 th/2, wire=tid
                ang = 0.5f * params[tid * 3 + 1];
            } else if (tid < 8) {                // layer0 A = -(phi+om)/2
                int q = tid - 4;
                ang = -0.5f * (params[q * 3 + 0] + params[q * 3 + 2]);
            } else if (tid < 12) {               // layer0 B = (phi-om)/2
                int q = tid - 8;
                ang = 0.5f * (params[q * 3 + 0] - params[q * 3 + 2]);
            } else if (tid == 12) {              // fold10 = phi[1][0]
                ang = params[4 * 3 + 0];
            } else if (tid < 21) {               // RY th/2, layers 1..2
                int idx = tid - 13, l = 1 + (idx >> 2), q = idx & 3;
                ang = 0.5f * params[(l * 4 + q) * 3 + 1];
            } else if (tid < 24) {               // phi[1][q], q=1..3
                int q = tid - 20;
                ang = params[(4 + q) * 3 + 0];
            } else if (tid < 28) {               // om_eff[q] = om[1][q] (+phi[2][0] q=0)
                int q = tid - 24;
                ang = params[(4 + q) * 3 + 2] + (q == 0 ? params[8 * 3 + 0] : 0.0f);
            } else {                             // phi[2][q], q=1..3
                int q = tid - 27;
                ang = params[(8 + q) * 3 + 0];
            }
            float s, c; __sincosf(ang, &s, &c);
            s_ph[tid] = make_float2(c, s);
            if (tid >= 13 && tid < 21) {
                // Givens constants: T = tan(th/2) = S/C
                int g = tid - 13;
                float T = __fdividef(s, c);
                s_ry[g][0] = pk(T, T);
                s_ry[g][1] = pk(-T, -T);
            }
        }
        __syncwarp();
        if (tid < 16) {
            // D23[k] = e^{i om.bits(k)} * e^{i phi2.bits(P(k))}, P = CNOT1 chain
            int k = tid;
            float2 o0 = s_ph[24], o1 = s_ph[25], o2 = s_ph[26], o3 = s_ph[27];
            float2 q1 = s_ph[28], q2 = s_ph[29], q3 = s_ph[30];
            float r = 1.0f, im = 0.0f;
            #define MULP(p) { float nr = r*(p).x - im*(p).y, ni = r*(p).y + im*(p).x; r = nr; im = ni; }
            if (k & 8) MULP(o0);
            if (k & 4) MULP(o1);
            if (k & 2) MULP(o2);
            if (k & 1) MULP(o3);
            {
                int b3 = (k >> 3) & 1, b2 = (k >> 2) & 1, b1 = (k >> 1) & 1, b0 = k & 1;
                int c2 = b2 ^ b3, c1 = b1 ^ c2, c0 = b0 ^ c1;
                if (c2) MULP(q1);
                if (c1) MULP(q2);
                if (c0) MULP(q3);
            }
            s_d23[k][0] = pk(r, r);
            s_d23[k][1] = pk(im, im);
        } else if (tid < 24) {
            // D1[m]: phases over bits (b2,b1,b0) = wires (1,2,3)
            int m = tid - 16;
            float2 p1 = s_ph[21], p2 = s_ph[22], p3 = s_ph[23];
            float r = 1.0f, im = 0.0f;
            if (m & 4) { r = p1.x; im = p1.y; }
            if (m & 2) MULP(p2);
            if (m & 1) MULP(p3);
            #undef MULP
            s_d1[m][0] = pk(r, r);
            s_d1[m][1] = pk(im, im);
        } else if (tid < 28) {
            // layer-0 dense gate
            int q = tid - 24;
            float2 T = s_ph[q], A = s_ph[4 + q], Bp = s_ph[8 + q];
            float ar =  T.x * A.x,  ai =  T.x * A.y;
            float br = -T.y * Bp.x, bi = -T.y * Bp.y;
            float cr = -br, ci = bi;   // -conj(b)
            float dr =  ar, di = -ai;  //  conj(a)
            if (q == 0) {              // fold phi[1][0] into row 2
                float2 F = s_ph[12];
                float cr2 = cr * F.x - ci * F.y, ci2 = cr * F.y + ci * F.x;
                float dr2 = dr * F.x - di * F.y, di2 = dr * F.y + di * F.x;
                cr = cr2; ci = ci2; dr = dr2; di = di2;
            }
            s_l0[q][0] = pk(ar, ar); s_l0[q][1] = pk(ai, ai);
            s_l0[q][2] = pk(br, br); s_l0[q][3] = pk(bi, bi);
            s_l0[q][4] = pk(cr, cr); s_l0[q][5] = pk(ci, ci);
            s_l0[q][6] = pk(dr, dr); s_l0[q][7] = pk(di, di);
        } else if (tid == 28) {
            // K^2 = (prod of the 8 RY cos(th/2))^2
            float kp = 1.0f;
            #pragma unroll
            for (int g = 0; g < 8; ++g) kp *= s_ph[13 + g].x;
            float k2 = kp * kp;
            s_k2 = pk(k2, k2);
        }
    }

    // ---- Pre-barrier per-thread math (overlaps the prologue) --------------
    u64 tc[4], ts[4];
    {
        float s0, c0, s1, c1;
        __sincosf(0.5f * xa.x, &s0, &c0); __sincosf(0.5f * xb.x, &s1, &c1);
        tc[0] = pk(c0, c1); ts[0] = pk(s0, s1);
        __sincosf(0.5f * xa.y, &s0, &c0); __sincosf(0.5f * xb.y, &s1, &c1);
        tc[1] = pk(c0, c1); ts[1] = pk(s0, s1);
        __sincosf(0.5f * xa.z, &s0, &c0); __sincosf(0.5f * xb.z, &s1, &c1);
        tc[2] = pk(c0, c1); ts[2] = pk(s0, s1);
        __sincosf(0.5f * xa.w, &s0, &c0); __sincosf(0.5f * xb.w, &s1, &c1);
        tc[3] = pk(c0, c1); ts[3] = pk(s0, s1);
    }

    // Encoding per wire: x_i = RY(x_{i+3}) RX(x_{i+2}) RZ(x_{i+1}) RY(x_i) |0>
    u64 xw[4][4];  // x0r, x0i, x1r, x1i per wire
    #pragma unroll
    for (int i = 0; i < 4; ++i) {
        u64 c1 = tc[i],           s1 = ts[i];
        u64 c2 = tc[(i + 1) & 3], s2 = ts[(i + 1) & 3];
        u64 c3 = tc[(i + 2) & 3], s3 = ts[(i + 2) & 3];
        u64 c4 = tc[(i + 3) & 3], s4 = ts[(i + 3) & 3];
        u64 a_r = f2mul(c1, c2), a_i = f2neg(f2mul(c1, s2));
        u64 b_r = f2mul(s1, c2), b_i = f2mul(s1, s2);
        u64 ns3 = f2neg(s3);
        u64 w0r = f2fma(c3, a_r, f2mul(s3,  b_i));
        u64 w0i = f2fma(c3, a_i, f2mul(ns3, b_r));
        u64 w1r = f2fma(c3, b_r, f2mul(s3,  a_i));
        u64 w1i = f2fma(c3, b_i, f2mul(ns3, a_r));
        u64 ns4 = f2neg(s4);
        xw[i][0] = f2fma(c4, w0r, f2mul(ns4, w1r));
        xw[i][1] = f2fma(c4, w0i, f2mul(ns4, w1i));
        xw[i][2] = f2fma(s4, w0r, f2mul(c4,  w1r));
        xw[i][3] = f2fma(s4, w0i, f2mul(c4,  w1i));
    }

    __syncthreads();
    if (!active) return;

    // ---- Layer-0 dense gate per wire (negations via ALU f2neg) ------------
    u64 vr[4][2], vi[4][2];
    #pragma unroll
    for (int i = 0; i < 4; ++i) {
        u64 x0r = xw[i][0], x0i = xw[i][1], x1r = xw[i][2], x1i = xw[i][3];
        u64 ar = s_l0[i][0], ai = s_l0[i][1], br = s_l0[i][2], bi = s_l0[i][3];
        u64 cr = s_l0[i][4], ci = s_l0[i][5], dr = s_l0[i][6], di = s_l0[i][7];
        u64 nai = f2neg(ai), nbi = f2neg(bi), nci = f2neg(ci), ndi = f2neg(di);
        vr[i][0] = f2fma(ar, x0r, f2fma(nai, x0i, f2fma(br, x1r, f2mul(nbi, x1i))));
        vi[i][0] = f2fma(ar, x0i, f2fma(ai,  x0r, f2fma(br, x1i, f2mul(bi,  x1r))));
        vr[i][1] = f2fma(cr, x0r, f2fma(nci, x0i, f2fma(dr, x1r, f2mul(ndi, x1i))));
        vi[i][1] = f2fma(cr, x0i, f2fma(ci,  x0r, f2fma(dr, x1i, f2mul(di,  x1r))));
    }

    // progressive tensor product -> 16 amplitudes (index = b3 b2 b1 b0)
    u64 w2r[4], w2i[4], w3r[8], w3i[8], sr[16], si[16];
    #pragma unroll
    for (int k = 0; k < 4; ++k)
        cmul(vr[0][k >> 1], vi[0][k >> 1], vr[1][k & 1], vi[1][k & 1], w2r[k], w2i[k]);
    #pragma unroll
    for (int k = 0; k < 8; ++k)
        cmul(w2r[k >> 1], w2i[k >> 1], vr[2][k & 1], vi[2][k & 1], w3r[k], w3i[k]);
    #pragma unroll
    for (int k = 0; k < 16; ++k)
        cmul(w3r[k >> 1], w3i[k >> 1], vr[3][k & 1], vi[3][k & 1], sr[k], si[k]);

    // CNOT0 chain (free register permutation)
    SWAP_AMP(8, 12); SWAP_AMP(9, 13); SWAP_AMP(10, 14); SWAP_AMP(11, 15);
    SWAP_AMP(4, 6);  SWAP_AMP(5, 7);  SWAP_AMP(12, 14); SWAP_AMP(13, 15);
    SWAP_AMP(2, 3);  SWAP_AMP(6, 7);  SWAP_AMP(10, 11); SWAP_AMP(14, 15);

    // D1: merged phi_1 diagonal (amps m, m+8 share a phase; m=0 identity)
    #pragma unroll
    for (int m = 1; m < 8; ++m) {
        u64 pr = s_d1[m][0], pi = s_d1[m][1], npi = f2neg(pi);
        u64 r = f2fma(sr[m], pr, f2mul(si[m], npi));
        si[m]   = f2fma(sr[m], pi, f2mul(si[m], pr));
        sr[m]   = r;
        r       = f2fma(sr[m + 8], pr, f2mul(si[m + 8], npi));
        si[m+8] = f2fma(sr[m + 8], pi, f2mul(si[m + 8], pr));
        sr[m+8] = r;
    }

    // RY(th_1) on all wires (Givens form)
    {
        u64 ta = s_ry[0][0], na = s_ry[0][1];
        u64 tb = s_ry[1][0], nb = s_ry[1][1];
        ry_givens<8>(sr, si, ta, na);
        ta = s_ry[2][0]; na = s_ry[2][1];
        ry_givens<4>(sr, si, tb, nb);
        tb = s_ry[3][0]; nb = s_ry[3][1];
        ry_givens<2>(sr, si, ta, na);
        ry_givens<1>(sr, si, tb, nb);
    }

    // D23: merged om_1 + pullback(phi_2) diagonal (k=0 identity)
    #pragma unroll
    for (int k = 1; k < 16; ++k) {
        u64 pr = s_d23[k][0], pi = s_d23[k][1], npi = f2neg(pi);
        u64 r = f2fma(sr[k], pr, f2mul(si[k], npi));
        si[k] = f2fma(sr[k], pi, f2mul(si[k], pr));
        sr[k] = r;
    }

    // CNOT1 chain (free)
    SWAP_AMP(8, 12); SWAP_AMP(9, 13); SWAP_AMP(10, 14); SWAP_AMP(11, 15);
    SWAP_AMP(4, 6);  SWAP_AMP(5, 7);  SWAP_AMP(12, 14); SWAP_AMP(13, 15);
    SWAP_AMP(2, 3);  SWAP_AMP(6, 7);  SWAP_AMP(10, 11); SWAP_AMP(14, 15);

    // RY(th_2) on all wires (Givens form; om_2 dropped before measurement)
    {
        u64 ta = s_ry[4][0], na = s_ry[4][1];
        u64 tb = s_ry[5][0], nb = s_ry[5][1];
        ry_givens<8>(sr, si, ta, na);
        ta = s_ry[6][0]; na = s_ry[6][1];
        ry_givens<4>(sr, si, tb, nb);
        tb = s_ry[7][0]; nb = s_ry[7][1];
        ry_givens<2>(sr, si, ta, na);
        ry_givens<1>(sr, si, tb, nb);
    }

    // CNOT2 chain (free)
    SWAP_AMP(8, 12); SWAP_AMP(9, 13); SWAP_AMP(10, 14); SWAP_AMP(11, 15);
    SWAP_AMP(4, 6);  SWAP_AMP(5, 7);  SWAP_AMP(12, 14); SWAP_AMP(13, 15);
    SWAP_AMP(2, 3);  SWAP_AMP(6, 7);  SWAP_AMP(10, 11); SWAP_AMP(14, 15);

    // probabilities (2-distinct-operand FMAs: rt2)
    u64 p[16];
    #pragma unroll
    for (int k = 0; k < 16; ++k)
        p[k] = f2fma(sr[k], sr[k], f2mul(si[k], si[k]));

    // Butterfly (partial Walsh) reduction, scaled by K^2
    u64 a[8], d[8];
    #pragma unroll
    for (int k = 0; k < 8; ++k) {
        a[k] = f2add(p[2 * k], p[2 * k + 1]);
        d[k] = f2sub(p[2 * k], p[2 * k + 1]);
    }
    u64 k2 = s_k2;
    u64 z3 = f2add(f2add(f2add(d[0], d[1]), f2add(d[2], d[3])),
                   f2add(f2add(d[4], d[5]), f2add(d[6], d[7])));
    u64 b[4], e[4];
    #pragma unroll
    for (int k = 0; k < 4; ++k) {
        b[k] = f2add(a[2 * k], a[2 * k + 1]);
        e[k] = f2sub(a[2 * k], a[2 * k + 1]);
    }
    u64 z2 = f2add(f2add(e[0], e[1]), f2add(e[2], e[3]));
    u64 c0 = f2add(b[0], b[1]), c1 = f2add(b[2], b[3]);
    u64 z1 = f2add(f2sub(b[0], b[1]), f2sub(b[2], b[3]));
    u64 z0 = f2sub(c0, c1);
    z0 = f2mul(z0, k2); z1 = f2mul(z1, k2);
    z2 = f2mul(z2, k2); z3 = f2mul(z3, k2);

    float z0a, z0b, z1a, z1b, z2a, z2b, z3a, z3b;
    upk(z0, z0a, z0b); upk(z1, z1a, z1b);
    upk(z2, z2a, z2b); upk(z3, z3a, z3b);
    out4[t]        = make_float4(z0a, z1a, z2a, z3a);
    out4[t + half] = make_float4(z0b, z1b, z2b, z3b);
}

// ---------------------------------------------------------------------------
extern "C" void kernel_launch(void* const* d_in, const int* in_sizes, int n_in,
                              void* d_out, int out_size) {
    const float* x      = (const float*)d_in[0];   // (B, 4) float32
    const float* params = (const float*)d_in[1];   // (3, 4, 3) float32
    float* out          = (float*)d_out;           // (B, 4) float32

    int B = in_sizes[0] / 4;
    int half = B / 2;

    const int threads = 256;
    int blocks = (half + threads - 1) / threads;
    qenc_kernel<<<blocks, threads>>>((const float4*)x, (float4*)out, params, half);
}

// round 11
// speedup vs baseline: 1.0076x; 1.0076x over previous
#include <cuda_runtime.h>
#include <math.h>

typedef unsigned long long u64;

// ---------------------------------------------------------------------------
// Precomputed gate tables (lane-duplicated f32x2 constants, 16B records).
// Written by a 1-warp precompute kernel; read by the main kernel via __ldg
// (uniform address -> 1 sector, L1-resident after first touch).
// ---------------------------------------------------------------------------
struct Tab {
    ulonglong2 l0[4][4];   // [q]: (ar,ai) (br,bi) (cr,ci) (dr,di)
    ulonglong2 ry[8];      // (T, -T)      gate g = 4*(l-1)+q
    ulonglong2 d1[8];      // (pr, pi)
    ulonglong2 d23[16];    // (pr, pi)
    ulonglong2 k2;         // ((prod cos)^2, unused)
};
__device__ __align__(16) Tab g_tab;

// ---------------------------------------------------------------------------
// f32x2 packed helpers (Blackwell dual-rate FP32 path)
// ---------------------------------------------------------------------------
__device__ __forceinline__ u64 pk(float lo, float hi) {
    u64 r;
    asm("mov.b64 %0, {%1,%2};" : "=l"(r) : "f"(lo), "f"(hi));
    return r;
}
__device__ __forceinline__ void upk(u64 v, float& lo, float& hi) {
    asm("mov.b64 {%0,%1}, %2;" : "=f"(lo), "=f"(hi) : "l"(v));
}
__device__ __forceinline__ u64 f2mul(u64 a, u64 b) {
    u64 r; asm("mul.rn.f32x2 %0, %1, %2;" : "=l"(r) : "l"(a), "l"(b)); return r;
}
__device__ __forceinline__ u64 f2add(u64 a, u64 b) {
    u64 r; asm("add.rn.f32x2 %0, %1, %2;" : "=l"(r) : "l"(a), "l"(b)); return r;
}
__device__ __forceinline__ u64 f2fma(u64 a, u64 b, u64 c) {
    u64 r; asm("fma.rn.f32x2 %0, %1, %2, %3;" : "=l"(r) : "l"(a), "l"(b), "l"(c)); return r;
}
__device__ __forceinline__ u64 f2sub(u64 a, u64 b) {
    u64 r; asm("sub.rn.f32x2 %0, %1, %2;" : "=l"(r) : "l"(a), "l"(b)); return r;
}
__device__ __forceinline__ u64 f2neg(u64 a) {
    return a ^ 0x8000000080000000ULL;  // sign-bit flip both lanes (ALU pipe)
}

// complex multiply, sub-form: 5 issue slots, all fma-pipe
__device__ __forceinline__ void cmul(u64 ar, u64 ai, u64 br, u64 bi, u64& cr, u64& ci) {
    cr = f2sub(f2mul(ar, br), f2mul(ai, bi));
    ci = f2fma(ar, bi, f2mul(ai, br));
}

// ---------------------------------------------------------------------------
// Precompute kernel: one warp builds all gate tables.
//   Rot(phi,th,om) = RZ(om) RY(th) RZ(phi); layer-0 dense per wire (wire0
//   absorbs phi_{1,0} fold); D1 = merged phi_1 diagonal; D23 = om_1 (+
//   phi_{2,0} on wire0) * CNOT1-pullback(phi_2); RY in Givens form
//   cos*(I + T*J) with K^2 = (prod cos)^2 applied at the end; om_2 dropped.
// ---------------------------------------------------------------------------
__global__ void precompute_kernel(const float* __restrict__ params) {
    __shared__ float2 s_ph[32];
    const int tid = threadIdx.x;

    if (tid < 31) {
        float ang;
        if (tid < 4) {                       // layer0 th/2, wire=tid
            ang = 0.5f * params[tid * 3 + 1];
        } else if (tid < 8) {                // layer0 A = -(phi+om)/2
            int q = tid - 4;
            ang = -0.5f * (params[q * 3 + 0] + params[q * 3 + 2]);
        } else if (tid < 12) {               // layer0 B = (phi-om)/2
            int q = tid - 8;
            ang = 0.5f * (params[q * 3 + 0] - params[q * 3 + 2]);
        } else if (tid == 12) {              // fold10 = phi[1][0]
            ang = params[4 * 3 + 0];
        } else if (tid < 21) {               // RY th/2, layers 1..2
            int idx = tid - 13, l = 1 + (idx >> 2), q = idx & 3;
            ang = 0.5f * params[(l * 4 + q) * 3 + 1];
        } else if (tid < 24) {               // phi[1][q], q=1..3
            int q = tid - 20;
            ang = params[(4 + q) * 3 + 0];
        } else if (tid < 28) {               // om_eff[q] = om[1][q] (+phi[2][0] q=0)
            int q = tid - 24;
            ang = params[(4 + q) * 3 + 2] + (q == 0 ? params[8 * 3 + 0] : 0.0f);
        } else {                             // phi[2][q], q=1..3
            int q = tid - 27;
            ang = params[(8 + q) * 3 + 0];
        }
        float s, c; sincosf(ang, &s, &c);    // full-precision: runs once
        s_ph[tid] = make_float2(c, s);
        if (tid >= 13 && tid < 21) {
            int g = tid - 13;
            float T = s / c;                 // tan(th/2)
            g_tab.ry[g] = make_ulonglong2(pk(T, T), pk(-T, -T));
        }
    }
    __syncwarp();

    if (tid < 16) {
        // D23[k] = e^{i om.bits(k)} * e^{i phi2.bits(P(k))}, P = CNOT1 chain
        int k = tid;
        float2 o0 = s_ph[24], o1 = s_ph[25], o2 = s_ph[26], o3 = s_ph[27];
        float2 q1 = s_ph[28], q2 = s_ph[29], q3 = s_ph[30];
        float r = 1.0f, im = 0.0f;
        #define MULP(p) { float nr = r*(p).x - im*(p).y, ni = r*(p).y + im*(p).x; r = nr; im = ni; }
        if (k & 8) MULP(o0);
        if (k & 4) MULP(o1);
        if (k & 2) MULP(o2);
        if (k & 1) MULP(o3);
        {
            int b3 = (k >> 3) & 1, b2 = (k >> 2) & 1, b1 = (k >> 1) & 1, b0 = k & 1;
            int c2 = b2 ^ b3, c1 = b1 ^ c2, c0 = b0 ^ c1;
            if (c2) MULP(q1);
            if (c1) MULP(q2);
            if (c0) MULP(q3);
        }
        g_tab.d23[k] = make_ulonglong2(pk(r, r), pk(im, im));
    } else if (tid < 24) {
        // D1[m]: phases over bits (b2,b1,b0) = wires (1,2,3)
        int m = tid - 16;
        float2 p1 = s_ph[21], p2 = s_ph[22], p3 = s_ph[23];
        float r = 1.0f, im = 0.0f;
        if (m & 4) { r = p1.x; im = p1.y; }
        if (m & 2) MULP(p2);
        if (m & 1) MULP(p3);
        #undef MULP
        g_tab.d1[m] = make_ulonglong2(pk(r, r), pk(im, im));
    } else if (tid < 28) {
        // layer-0 dense gate
        int q = tid - 24;
        float2 T = s_ph[q], A = s_ph[4 + q], Bp = s_ph[8 + q];
        float ar =  T.x * A.x,  ai =  T.x * A.y;
        float br = -T.y * Bp.x, bi = -T.y * Bp.y;
        float cr = -br, ci = bi;   // -conj(b)
        float dr =  ar, di = -ai;  //  conj(a)
        if (q == 0) {              // fold phi[1][0] into row 2
            float2 F = s_ph[12];
            float cr2 = cr * F.x - ci * F.y, ci2 = cr * F.y + ci * F.x;
            float dr2 = dr * F.x - di * F.y, di2 = dr * F.y + di * F.x;
            cr = cr2; ci = ci2; dr = dr2; di = di2;
        }
        g_tab.l0[q][0] = make_ulonglong2(pk(ar, ar), pk(ai, ai));
        g_tab.l0[q][1] = make_ulonglong2(pk(br, br), pk(bi, bi));
        g_tab.l0[q][2] = make_ulonglong2(pk(cr, cr), pk(ci, ci));
        g_tab.l0[q][3] = make_ulonglong2(pk(dr, dr), pk(di, di));
    } else if (tid == 28) {
        float kp = 1.0f;
        #pragma unroll
        for (int g = 0; g < 8; ++g) kp *= s_ph[13 + g].x;
        float k2 = kp * kp;
        g_tab.k2 = make_ulonglong2(pk(k2, k2), 0ULL);
    }
}

// ---------------------------------------------------------------------------
// Givens-form RY on qubit at bit M:  RY = cos(th/2) * [[1, -T],[T, 1]].
// 4 FMA per pair, dependency depth 1.
// ---------------------------------------------------------------------------
template<int M>
__device__ __forceinline__ void ry_givens(u64* sr, u64* si, u64 tt, u64 nt) {
    #pragma unroll
    for (int i = 0; i < 16; ++i) {
        if (i & M) continue;
        const int j = i | M;
        u64 xr = f2fma(nt, sr[j], sr[i]);
        u64 xi = f2fma(nt, si[j], si[i]);
        sr[j] = f2fma(tt, sr[i], sr[j]);
        si[j] = f2fma(tt, si[i], si[j]);
        sr[i] = xr; si[i] = xi;
    }
}

#define SWAP_AMP(a, b) do { u64 _t = sr[a]; sr[a] = sr[b]; sr[b] = _t; \
                            _t = si[a]; si[a] = si[b]; si[b] = _t; } while (0)

// ---------------------------------------------------------------------------
// Main kernel: straight-line, NO smem, NO barrier, NO prologue (round-3
// structure, which ran at 100% of the rt3 bank-limited fma ceiling).
// Constants arrive via uniform __ldg of 16B records (L1-resident).
// Each thread simulates 2 batch elements packed into f32x2 lanes.
// ---------------------------------------------------------------------------
__global__ void __launch_bounds__(256, 3)
qenc_kernel(const float4* __restrict__ x4, float4* __restrict__ out4, int half) {
    const int t = blockIdx.x * blockDim.x + threadIdx.x;
    if (t >= half) return;

    float4 xa = x4[t];
    float4 xb = x4[t + half];

    // half-angle trig for the 4 encoding angles, packed over 2 elements
    u64 tc[4], ts[4];
    {
        float s0, c0, s1, c1;
        __sincosf(0.5f * xa.x, &s0, &c0); __sincosf(0.5f * xb.x, &s1, &c1);
        tc[0] = pk(c0, c1); ts[0] = pk(s0, s1);
        __sincosf(0.5f * xa.y, &s0, &c0); __sincosf(0.5f * xb.y, &s1, &c1);
        tc[1] = pk(c0, c1); ts[1] = pk(s0, s1);
        __sincosf(0.5f * xa.z, &s0, &c0); __sincosf(0.5f * xb.z, &s1, &c1);
        tc[2] = pk(c0, c1); ts[2] = pk(s0, s1);
        __sincosf(0.5f * xa.w, &s0, &c0); __sincosf(0.5f * xb.w, &s1, &c1);
        tc[3] = pk(c0, c1); ts[3] = pk(s0, s1);
    }

    // Encoding + layer-0 dense gate per wire, on product factors:
    //   v_i = G_{0,i} * RY(x_{i+3}) RX(x_{i+2}) RZ(x_{i+1}) RY(x_i) |0>
    u64 vr[4][2], vi[4][2];
    #pragma unroll
    for (int i = 0; i < 4; ++i) {
        u64 c1 = tc[i],           s1 = ts[i];
        u64 c2 = tc[(i + 1) & 3], s2 = ts[(i + 1) & 3];
        u64 c3 = tc[(i + 2) & 3], s3 = ts[(i + 2) & 3];
        u64 c4 = tc[(i + 3) & 3], s4 = ts[(i + 3) & 3];
        u64 a_r = f2mul(c1, c2), a_i = f2neg(f2mul(c1, s2));
        u64 b_r = f2mul(s1, c2), b_i = f2mul(s1, s2);
        u64 ns3 = f2neg(s3);
        u64 w0r = f2fma(c3, a_r, f2mul(s3,  b_i));
        u64 w0i = f2fma(c3, a_i, f2mul(ns3, b_r));
        u64 w1r = f2fma(c3, b_r, f2mul(s3,  a_i));
        u64 w1i = f2fma(c3, b_i, f2mul(ns3, a_r));
        u64 ns4 = f2neg(s4);
        u64 x0r = f2fma(c4, w0r, f2mul(ns4, w1r));
        u64 x0i = f2fma(c4, w0i, f2mul(ns4, w1i));
        u64 x1r = f2fma(s4, w0r, f2mul(c4,  w1r));
        u64 x1i = f2fma(s4, w0i, f2mul(c4,  w1i));
        ulonglong2 ra = __ldg(&g_tab.l0[i][0]);
        ulonglong2 rb = __ldg(&g_tab.l0[i][1]);
        ulonglong2 rc = __ldg(&g_tab.l0[i][2]);
        ulonglong2 rd = __ldg(&g_tab.l0[i][3]);
        u64 ar = ra.x, ai = ra.y, br = rb.x, bi = rb.y;
        u64 cr = rc.x, ci = rc.y, dr = rd.x, di = rd.y;
        u64 nai = f2neg(ai), nbi = f2neg(bi), nci = f2neg(ci), ndi = f2neg(di);
        vr[i][0] = f2fma(ar, x0r, f2fma(nai, x0i, f2fma(br, x1r, f2mul(nbi, x1i))));
        vi[i][0] = f2fma(ar, x0i, f2fma(ai,  x0r, f2fma(br, x1i, f2mul(bi,  x1r))));
        vr[i][1] = f2fma(cr, x0r, f2fma(nci, x0i, f2fma(dr, x1r, f2mul(ndi, x1i))));
        vi[i][1] = f2fma(cr, x0i, f2fma(ci,  x0r, f2fma(dr, x1i, f2mul(di,  x1r))));
    }

    // progressive tensor product -> 16 amplitudes (index = b3 b2 b1 b0)
    u64 w2r[4], w2i[4], w3r[8], w3i[8], sr[16], si[16];
    #pragma unroll
    for (int k = 0; k < 4; ++k)
        cmul(vr[0][k >> 1], vi[0][k >> 1], vr[1][k & 1], vi[1][k & 1], w2r[k], w2i[k]);
    #pragma unroll
    for (int k = 0; k < 8; ++k)
        cmul(w2r[k >> 1], w2i[k >> 1], vr[2][k & 1], vi[2][k & 1], w3r[k], w3i[k]);
    #pragma unroll
    for (int k = 0; k < 16; ++k)
        cmul(w3r[k >> 1], w3i[k >> 1], vr[3][k & 1], vi[3][k & 1], sr[k], si[k]);

    // CNOT0 chain (free register permutation)
    SWAP_AMP(8, 12); SWAP_AMP(9, 13); SWAP_AMP(10, 14); SWAP_AMP(11, 15);
    SWAP_AMP(4, 6);  SWAP_AMP(5, 7);  SWAP_AMP(12, 14); SWAP_AMP(13, 15);
    SWAP_AMP(2, 3);  SWAP_AMP(6, 7);  SWAP_AMP(10, 11); SWAP_AMP(14, 15);

    // D1: merged phi_1 diagonal (amps m, m+8 share a phase; m=0 identity)
    #pragma unroll
    for (int m = 1; m < 8; ++m) {
        ulonglong2 v = __ldg(&g_tab.d1[m]);
        u64 pr = v.x, pi = v.y, npi = f2neg(pi);
        u64 r = f2fma(sr[m], pr, f2mul(si[m], npi));
        si[m]   = f2fma(sr[m], pi, f2mul(si[m], pr));
        sr[m]   = r;
        r       = f2fma(sr[m + 8], pr, f2mul(si[m + 8], npi));
        si[m+8] = f2fma(sr[m + 8], pi, f2mul(si[m + 8], pr));
        sr[m+8] = r;
    }

    // RY(th_1) on all wires (Givens form)
    {
        ulonglong2 g0 = __ldg(&g_tab.ry[0]);
        ulonglong2 g1 = __ldg(&g_tab.ry[1]);
        ry_givens<8>(sr, si, g0.x, g0.y);
        ulonglong2 g2 = __ldg(&g_tab.ry[2]);
        ry_givens<4>(sr, si, g1.x, g1.y);
        ulonglong2 g3 = __ldg(&g_tab.ry[3]);
        ry_givens<2>(sr, si, g2.x, g2.y);
        ry_givens<1>(sr, si, g3.x, g3.y);
    }

    // D23: merged om_1 + pullback(phi_2) diagonal (k=0 identity)
    #pragma unroll
    for (int k = 1; k < 16; ++k) {
        ulonglong2 v = __ldg(&g_tab.d23[k]);
        u64 pr = v.x, pi = v.y, npi = f2neg(pi);
        u64 r = f2fma(sr[k], pr, f2mul(si[k], npi));
        si[k] = f2fma(sr[k], pi, f2mul(si[k], pr));
        sr[k] = r;
    }

    // CNOT1 chain (free)
    SWAP_AMP(8, 12); SWAP_AMP(9, 13); SWAP_AMP(10, 14); SWAP_AMP(11, 15);
    SWAP_AMP(4, 6);  SWAP_AMP(5, 7);  SWAP_AMP(12, 14); SWAP_AMP(13, 15);
    SWAP_AMP(2, 3);  SWAP_AMP(6, 7);  SWAP_AMP(10, 11); SWAP_AMP(14, 15);

    // RY(th_2) on all wires (Givens form; om_2 dropped before measurement)
    {
        ulonglong2 g4 = __ldg(&g_tab.ry[4]);
        ulonglong2 g5 = __ldg(&g_tab.ry[5]);
        ry_givens<8>(sr, si, g4.x, g4.y);
        ulonglong2 g6 = __ldg(&g_tab.ry[6]);
        ry_givens<4>(sr, si, g5.x, g5.y);
        ulonglong2 g7 = __ldg(&g_tab.ry[7]);
        ry_givens<2>(sr, si, g6.x, g6.y);
        ry_givens<1>(sr, si, g7.x, g7.y);
    }

    // CNOT2 chain (free)
    SWAP_AMP(8, 12); SWAP_AMP(9, 13); SWAP_AMP(10, 14); SWAP_AMP(11, 15);
    SWAP_AMP(4, 6);  SWAP_AMP(5, 7);  SWAP_AMP(12, 14); SWAP_AMP(13, 15);
    SWAP_AMP(2, 3);  SWAP_AMP(6, 7);  SWAP_AMP(10, 11); SWAP_AMP(14, 15);

    // probabilities (2-distinct-operand FMAs: rt2)
    u64 p[16];
    #pragma unroll
    for (int k = 0; k < 16; ++k)
        p[k] = f2fma(sr[k], sr[k], f2mul(si[k], si[k]));

    // Butterfly (partial Walsh) reduction, scaled by K^2
    u64 a[8], d[8];
    #pragma unroll
    for (int k = 0; k < 8; ++k) {
        a[k] = f2add(p[2 * k], p[2 * k + 1]);
        d[k] = f2sub(p[2 * k], p[2 * k + 1]);
    }
    u64 k2 = __ldg(&g_tab.k2).x;
    u64 z3 = f2add(f2add(f2add(d[0], d[1]), f2add(d[2], d[3])),
                   f2add(f2add(d[4], d[5]), f2add(d[6], d[7])));
    u64 b[4], e[4];
    #pragma unroll
    for (int k = 0; k < 4; ++k) {
        b[k] = f2add(a[2 * k], a[2 * k + 1]);
        e[k] = f2sub(a[2 * k], a[2 * k + 1]);
    }
    u64 z2 = f2add(f2add(e[0], e[1]), f2add(e[2], e[3]));
    u64 c0 = f2add(b[0], b[1]), c1 = f2add(b[2], b[3]);
    u64 z1 = f2add(f2sub(b[0], b[1]), f2sub(b[2], b[3]));
    u64 z0 = f2sub(c0, c1);
    z0 = f2mul(z0, k2); z1 = f2mul(z1, k2);
    z2 = f2mul(z2, k2); z3 = f2mul(z3, k2);

    float z0a, z0b, z1a, z1b, z2a, z2b, z3a, z3b;
    upk(z0, z0a, z0b); upk(z1, z1a, z1b);
    upk(z2, z2a, z2b); upk(z3, z3a, z3b);
    out4[t]        = make_float4(z0a, z1a, z2a, z3a);
    out4[t + half] = make_float4(z0b, z1b, z2b, z3b);
}

// ---------------------------------------------------------------------------
extern "C" void kernel_launch(void* const* d_in, const int* in_sizes, int n_in,
                              void* d_out, int out_size) {
    const float* x      = (const float*)d_in[0];   // (B, 4) float32
    const float* params = (const float*)d_in[1];   // (3, 4, 3) float32
    float* out          = (float*)d_out;           // (B, 4) float32

    int B = in_sizes[0] / 4;
    int half = B / 2;

    precompute_kernel<<<1, 32>>>(params);

    const int threads = 256;
    int blocks = (half + threads - 1) / threads;
    qenc_kernel<<<blocks, threads>>>((const float4*)x, (float4*)out, half);
}